// round 1
// baseline (speedup 1.0000x reference)
#include <cuda_runtime.h>

#define N   8192
#define D   192
#define BM  128
#define KC  32
#define LDA (BM + 4)   // 132 floats: keeps 16B row alignment for float4 LDS

// Device-global scratch (no allocations allowed in kernel_launch)
__device__ double g_sumsq;
__device__ double g_colsum[D];
__device__ double g_loss;
__device__ float  g_sq[N];
__device__ float  g_c;     // 1 / (bandwidth * 16)  == deepest kernel coefficient

// ---------------------------------------------------------------------------
__global__ void k_zero() {
    int t = threadIdx.x;
    if (t < D) g_colsum[t] = 0.0;
    if (t == 0) { g_sumsq = 0.0; g_loss = 0.0; }
}

// One warp per row: sq[r] = sum_k x[r][k]^2 ; also accumulate total sum of squares.
__global__ void k_rowsq(const float* __restrict__ x) {
    int lane = threadIdx.x & 31;
    int wid  = threadIdx.x >> 5;
    int row  = blockIdx.x * 8 + wid;
    const float* p = x + (size_t)row * D;
    float s = 0.f;
    #pragma unroll
    for (int k = lane; k < D; k += 32) { float v = p[k]; s = fmaf(v, v, s); }
    #pragma unroll
    for (int o = 16; o > 0; o >>= 1) s += __shfl_down_sync(0xffffffffu, s, o);
    if (lane == 0) {
        g_sq[row] = s;
        atomicAdd(&g_sumsq, (double)s);
    }
}

// Column sums (for ||sum_i x_i||^2). Thread k of each block sums 128 rows of col k.
__global__ void k_colsum(const float* __restrict__ x) {
    int k  = threadIdx.x;
    int r0 = blockIdx.x * 128;
    float s = 0.f;
    #pragma unroll 8
    for (int r = 0; r < 128; r++) s += x[(size_t)(r0 + r) * D + k];
    atomicAdd(&g_colsum[k], (double)s);
}

// bandwidth = [2n*sum(sq) - 2*||colsum||^2] / (n^2 - n) / KERNEL_MUL^(KERNEL_NUM/2)
__global__ void k_const() {
    double ss = 0.0;
    for (int k = 0; k < D; k++) { double v = g_colsum[k]; ss += v * v; }
    double sumL2 = 2.0 * (double)N * g_sumsq - 2.0 * ss;
    double bw = sumL2 / ((double)N * (double)N - (double)N);
    bw = bw * 0.25;                       // / 2^(5//2) = /4
    g_c = (float)(1.0 / (bw * 16.0));     // coefficient of deepest (k=4) kernel
}

// ---------------------------------------------------------------------------
// Main fused Gram pass: 128x128 pair tile per block, 8x8 register micro-tile,
// epilogue computes the 5-kernel MMD contribution in-register (nothing stored).
// Upper-triangle blocks only; diagonal pairs handled analytically in k_final.
__global__ __launch_bounds__(256) void k_main(const float* __restrict__ x) {
    int bi = blockIdx.y, bj = blockIdx.x;
    if (bj < bi) return;

    __shared__ float As[KC][LDA];
    __shared__ float Bs[KC][LDA];
    __shared__ float red[256];

    int tid = threadIdx.x;
    int tx  = tid & 15;     // j direction
    int ty  = tid >> 4;     // i direction

    float acc[8][8];
    #pragma unroll
    for (int m = 0; m < 8; m++)
        #pragma unroll
        for (int n = 0; n < 8; n++) acc[m][n] = 0.f;

    const float* xa = x + (size_t)bi * BM * D;
    const float* xb = x + (size_t)bj * BM * D;

    for (int kc = 0; kc < D; kc += KC) {
        // Load 128x32 fp32 per operand, k-transposed into smem.
        #pragma unroll
        for (int v = 0; v < 4; v++) {
            int idx = v * 256 + tid;
            int row = idx >> 3;
            int kv  = (idx & 7) << 2;
            float4 fa = *(const float4*)(xa + (size_t)row * D + kc + kv);
            As[kv + 0][row] = fa.x; As[kv + 1][row] = fa.y;
            As[kv + 2][row] = fa.z; As[kv + 3][row] = fa.w;
            float4 fb = *(const float4*)(xb + (size_t)row * D + kc + kv);
            Bs[kv + 0][row] = fb.x; Bs[kv + 1][row] = fb.y;
            Bs[kv + 2][row] = fb.z; Bs[kv + 3][row] = fb.w;
        }
        __syncthreads();

        #pragma unroll
        for (int k = 0; k < KC; k++) {
            float af[8], bf[8];
            *(float4*)(af    ) = *(const float4*)&As[k][ty * 8];
            *(float4*)(af + 4) = *(const float4*)&As[k][ty * 8 + 4];
            *(float4*)(bf    ) = *(const float4*)&Bs[k][tx * 8];
            *(float4*)(bf + 4) = *(const float4*)&Bs[k][tx * 8 + 4];
            #pragma unroll
            for (int m = 0; m < 8; m++)
                #pragma unroll
                for (int n = 0; n < 8; n++)
                    acc[m][n] = fmaf(af[m], bf[n], acc[m][n]);
        }
        __syncthreads();
    }

    // Fused epilogue: L2 -> 1 exp + 4 squarings -> signed accumulate.
    float c = g_c;
    float sqi[8], sqj[8];
    #pragma unroll
    for (int m = 0; m < 8; m++) sqi[m] = g_sq[bi * BM + ty * 8 + m];
    #pragma unroll
    for (int n = 0; n < 8; n++) sqj[n] = g_sq[bj * BM + tx * 8 + n];

    bool diag = (bi == bj);
    float part = 0.f;
    #pragma unroll
    for (int m = 0; m < 8; m++) {
        int gi = bi * BM + ty * 8 + m;
        #pragma unroll
        for (int n = 0; n < 8; n++) {
            int gj = bj * BM + tx * 8 + n;
            // sigma_i*sigma_j = (-1)^(i+j); x2 for symmetry (pair counted once)
            float w = ((gi ^ gj) & 1) ? -2.f : 2.f;
            if (diag && gj <= gi) w = 0.f;   // strict upper triangle on diagonal blocks
            float L2 = fmaxf(sqi[m] + sqj[n] - 2.f * acc[m][n], 0.f);
            float t  = __expf(-L2 * c);      // arg in [-0.5, 0], ~2 ulp
            float t2 = t * t, t4 = t2 * t2, t8 = t4 * t4, t16 = t8 * t8;
            part = fmaf(w, t + t2 + t4 + t8 + t16, part);
        }
    }

    red[tid] = part;
    __syncthreads();
    #pragma unroll
    for (int o = 128; o > 0; o >>= 1) {
        if (tid < o) red[tid] += red[tid + o];
        __syncthreads();
    }
    if (tid == 0) atomicAdd(&g_loss, (double)red[0]);
}

// Diagonal contributes exactly 5 per row (L2_ii clamps to ~0, 5 kernels of 1).
__global__ void k_final(float* __restrict__ out) {
    double half = (double)(N / 2);
    out[0] = (float)((g_loss + 5.0 * (double)N) / (half * half));
}

// ---------------------------------------------------------------------------
extern "C" void kernel_launch(void* const* d_in, const int* in_sizes, int n_in,
                              void* d_out, int out_size) {
    const float* x = (const float*)d_in[0];
    float* out = (float*)d_out;

    k_zero  <<<1, 256>>>();
    k_rowsq <<<N / 8, 256>>>(x);
    k_colsum<<<64, D>>>(x);
    k_const <<<1, 1>>>();
    dim3 grid(N / BM, N / BM);
    k_main  <<<grid, 256>>>(x);
    k_final <<<1, 1>>>(out);
}

// round 3
// speedup vs baseline: 4.2370x; 4.2370x over previous
#include <cuda_runtime.h>
#include <cuda_fp16.h>
#include <cstdint>

#define N        8192
#define D        192
#define BM       128
#define NB       64
#define NTILES   2080          // NB*(NB+1)/2
#define TILE_BYTES (BM * D * 2)   // 49152 fp16 bytes per 128-row tile

// ---------------- device globals ----------------
__device__ double g_sumsq;
__device__ double g_colsum[D];
__device__ double g_loss;
__device__ float  g_sq[N];
__device__ float  g_c2;                    // log2(e) / (16*bandwidth)
__device__ uint4  g_xh[N * D * 2 / 16];    // fp16 x, row-major stride 384B, XOR-swizzled in 16B groups

// ---------------- helpers ----------------
__device__ __forceinline__ uint32_t smem_u32(const void* p) {
    uint32_t a;
    asm("{ .reg .u64 t; cvta.to.shared.u64 t, %1; cvt.u32.u64 %0, t; }" : "=r"(a) : "l"(p));
    return a;
}
#define MBAR_INIT(a, c) asm volatile("mbarrier.init.shared.b64 [%0], %1;" :: "r"(a), "r"(c) : "memory")
#define MBAR_INVAL(a)   asm volatile("mbarrier.inval.shared.b64 [%0];"    :: "r"(a) : "memory")
#define MBAR_EXPECT_TX(a, b) asm volatile("mbarrier.arrive.expect_tx.shared.b64 _, [%0], %1;" :: "r"(a), "r"(b) : "memory")
#define MBAR_WAIT(a, ph) do { \
    uint32_t _m = (a), _p = (ph), _d; \
    asm volatile("{ .reg .pred p; mbarrier.try_wait.parity.acquire.cta.shared::cta.b64 p, [%1], %2; selp.b32 %0,1,0,p; }" \
        : "=r"(_d) : "r"(_m), "r"(_p) : "memory"); \
    if (!_d) { asm volatile("{ .reg .pred P1; WL_%=: mbarrier.try_wait.parity.acquire.cta.shared::cta.b64 P1, [%0], %1, 0x989680; @P1 bra.uni WD_%=; bra.uni WL_%=; WD_%=: }" \
        :: "r"(_m), "r"(_p) : "memory"); } } while (0)

__device__ __forceinline__ void bulk_g2s(uint32_t dst, const void* src, uint32_t bytes, uint32_t mbar) {
    asm volatile("cp.async.bulk.shared::cluster.global.mbarrier::complete_tx::bytes [%0], [%1], %2, [%3];"
        :: "r"(dst), "l"(src), "r"(bytes), "r"(mbar) : "memory");
}
#define LDSM_X4(r0, r1, r2, r3, a) \
    asm volatile("ldmatrix.sync.aligned.m8n8.x4.shared.b16 {%0,%1,%2,%3}, [%4];" \
        : "=r"(r0), "=r"(r1), "=r"(r2), "=r"(r3) : "r"(a))
#define MMA16816(d, a, b0, b1) \
    asm volatile("mma.sync.aligned.m16n8k16.row.col.f32.f16.f16.f32 " \
        "{%0,%1,%2,%3},{%4,%5,%6,%7},{%8,%9},{%0,%1,%2,%3};" \
        : "+f"((d)[0]), "+f"((d)[1]), "+f"((d)[2]), "+f"((d)[3]) \
        : "r"((a)[0]), "r"((a)[1]), "r"((a)[2]), "r"((a)[3]), "r"(b0), "r"(b1))
__device__ __forceinline__ float ex2(float x) {
    float r; asm("ex2.approx.ftz.f32 %0, %1;" : "=f"(r) : "f"(x)); return r;
}

// ---------------- prologue ----------------
__global__ void k_zero() {
    int t = threadIdx.x;
    if (t < D) g_colsum[t] = 0.0;
    if (t == 0) { g_sumsq = 0.0; g_loss = 0.0; }
}

__global__ void k_rowsq(const float* __restrict__ x) {
    int lane = threadIdx.x & 31, wid = threadIdx.x >> 5;
    int row = blockIdx.x * 8 + wid;
    const float* p = x + (size_t)row * D;
    float s = 0.f;
    #pragma unroll
    for (int k = lane; k < D; k += 32) { float v = p[k]; s = fmaf(v, v, s); }
    #pragma unroll
    for (int o = 16; o > 0; o >>= 1) s += __shfl_down_sync(0xffffffffu, s, o);
    if (lane == 0) { g_sq[row] = s; atomicAdd(&g_sumsq, (double)s); }
}

__global__ void k_colsum(const float* __restrict__ x) {
    int k = threadIdx.x, r0 = blockIdx.x * 128;
    float s = 0.f;
    #pragma unroll 8
    for (int r = 0; r < 128; r++) s += x[(size_t)(r0 + r) * D + k];
    atomicAdd(&g_colsum[k], (double)s);
}

__global__ void k_const() {   // 192 threads
    __shared__ double sh[D];
    int t = threadIdx.x;
    double v = g_colsum[t];
    sh[t] = v * v;
    __syncthreads();
    if (t == 0) {
        double ss = 0.0;
        for (int k = 0; k < D; k++) ss += sh[k];
        double sumL2 = 2.0 * (double)N * g_sumsq - 2.0 * ss;
        double bw = sumL2 / ((double)N * (double)N - (double)N);
        bw *= 0.25;                                     // / KERNEL_MUL^(KERNEL_NUM//2)
        g_c2 = (float)(1.4426950408889634 / (bw * 16.0));
    }
}

// fp32 -> fp16 row-major (stride 384B), 16B group g of row r stored at g ^ (r&7)
__global__ void k_convert(const float* __restrict__ x) {
    int idx = blockIdx.x * 256 + threadIdx.x;    // 0..196607
    int r = idx / 24;
    int g = idx % 24;
    const float* src = x + (size_t)r * D + g * 8;
    float4 f0 = *(const float4*)src;
    float4 f1 = *(const float4*)(src + 4);
    half2 h[4];
    h[0] = __float22half2_rn(make_float2(f0.x, f0.y));
    h[1] = __float22half2_rn(make_float2(f0.z, f0.w));
    h[2] = __float22half2_rn(make_float2(f1.x, f1.y));
    h[3] = __float22half2_rn(make_float2(f1.z, f1.w));
    uint32_t dst = (uint32_t)r * 384u + (uint32_t)((g ^ (r & 7)) << 4);
    *(uint4*)((char*)g_xh + dst) = *(uint4*)h;
}

// ---------------- main HMMA tile kernel ----------------
// dyn smem (1024-aligned base): 0 sqi[128], 512 sqj[128], 1024 mbar, 1088 red[256],
// 3072 A tile (49152), 52224 B tile (49152) -> 101376; +1024 align slack
#define OFF_SQI  0
#define OFF_SQJ  512
#define OFF_MBAR 1024
#define OFF_RED  1088
#define OFF_A    3072
#define OFF_B    52224
#define SMEM_DYN (101376 + 1024)

__global__ __launch_bounds__(256, 2) void k_main() {
    extern __shared__ char dsm[];
    uint32_t sb = (smem_u32(dsm) + 1023u) & ~1023u;
    char* sp = dsm + (sb - smem_u32(dsm));

    int tid  = threadIdx.x;
    int wid  = tid >> 5, lane = tid & 31;
    int wM   = wid >> 2;          // 0..1 -> 64 rows each
    int wN   = wid & 3;           // 0..3 -> 32 cols each
    int gID  = lane >> 2;         // groupID
    int tig  = lane & 3;

    // triangular decode (exact)
    int t = blockIdx.x, bi = 0, rem = t;
    while (rem >= NB - bi) { rem -= NB - bi; bi++; }
    int bj = bi + rem;
    bool diag = (bi == bj);

    uint32_t mbar = sb + OFF_MBAR;
    if (tid == 0) MBAR_INIT(mbar, 1);

    // stage row norms
    if (tid < 128) ((float*)(sp + OFF_SQI))[tid] = g_sq[bi * BM + tid];
    else           ((float*)(sp + OFF_SQJ))[tid - 128] = g_sq[bj * BM + tid - 128];
    __syncthreads();

    if (tid == 0) {
        MBAR_EXPECT_TX(mbar, 2 * TILE_BYTES);
        const char* xh = (const char*)g_xh;
        bulk_g2s(sb + OFF_A, xh + (size_t)bi * TILE_BYTES, TILE_BYTES, mbar);
        bulk_g2s(sb + OFF_B, xh + (size_t)bj * TILE_BYTES, TILE_BYTES, mbar);
    }

    float acc[4][4][4];
    #pragma unroll
    for (int a = 0; a < 4; a++)
        #pragma unroll
        for (int b = 0; b < 4; b++)
            #pragma unroll
            for (int c = 0; c < 4; c++) acc[a][b][c] = 0.f;

    // ldmatrix base addresses (XOR swizzle: 16B group g of row r lives at g^(r&7))
    uint32_t swz   = (uint32_t)(lane & 7);
    uint32_t ahi   = (uint32_t)(lane >> 4);            // A k-half select
    uint32_t bhi   = (uint32_t)((lane >> 3) & 1);      // B k-half select
    uint32_t baseA = sb + OFF_A + (uint32_t)(wM * 64 + (lane & 15)) * 384u;
    uint32_t baseB = sb + OFF_B + (uint32_t)(wN * 32 + ((lane >> 4) << 3) + (lane & 7)) * 384u;

    MBAR_WAIT(mbar, 0);

    #pragma unroll
    for (int kg = 0; kg < 12; kg++) {
        uint32_t a[4][4], b[2][4];
        uint32_t ga = (uint32_t)(2 * kg) + ahi;
        uint32_t gb = (uint32_t)(2 * kg) + bhi;
        #pragma unroll
        for (int fm = 0; fm < 4; fm++) {
            uint32_t ad = baseA + (uint32_t)fm * 6144u + ((ga ^ swz) << 4);
            LDSM_X4(a[fm][0], a[fm][1], a[fm][2], a[fm][3], ad);
        }
        #pragma unroll
        for (int q = 0; q < 2; q++) {
            uint32_t bd = baseB + (uint32_t)q * 6144u + ((gb ^ swz) << 4);
            LDSM_X4(b[q][0], b[q][1], b[q][2], b[q][3], bd);
        }
        #pragma unroll
        for (int fm = 0; fm < 4; fm++)
            #pragma unroll
            for (int fn = 0; fn < 4; fn++)
                MMA16816(acc[fm][fn], a[fm], b[fn >> 1][(fn & 1) * 2], b[fn >> 1][(fn & 1) * 2 + 1]);
    }

    // ---------------- fused MMD epilogue ----------------
    float c2 = g_c2, tc2 = 2.f * c2, nc2 = -c2;
    const float* s_sqi = (const float*)(sp + OFF_SQI);
    const float* s_sqj = (const float*)(sp + OFF_SQJ);

    float nsi[8], nsj[8];
    #pragma unroll
    for (int fm = 0; fm < 4; fm++) {
        nsi[fm * 2 + 0] = nc2 * s_sqi[wM * 64 + fm * 16 + gID];
        nsi[fm * 2 + 1] = nc2 * s_sqi[wM * 64 + fm * 16 + gID + 8];
    }
    #pragma unroll
    for (int fn = 0; fn < 4; fn++) {
        nsj[fn * 2 + 0] = nc2 * s_sqj[wN * 32 + fn * 8 + tig * 2];
        nsj[fn * 2 + 1] = nc2 * s_sqj[wN * 32 + fn * 8 + tig * 2 + 1];
    }

    float part = 0.f;
    if (!diag) {
        float A0 = 0.f, A1 = 0.f;    // buckets by gj parity (== reg&1)
        #pragma unroll
        for (int fm = 0; fm < 4; fm++)
            #pragma unroll
            for (int fn = 0; fn < 4; fn++)
                #pragma unroll
                for (int r = 0; r < 4; r++) {
                    float arg = fminf(fmaf(acc[fm][fn][r], tc2,
                                           nsi[fm * 2 + (r >> 1)] + nsj[fn * 2 + (r & 1)]), 0.f);
                    float tt = ex2(arg);
                    float t2 = tt * tt, t4 = t2 * t2, t8 = t4 * t4;
                    float s1 = fmaf(tt, tt, tt);        // t + t^2
                    float s2 = fmaf(t4, t4, t4);        // t^4 + t^8
                    float ks = (s1 + s2) + t8 * t8;     // + t^16
                    if (r & 1) A1 += ks; else A0 += ks;
                }
        part = (gID & 1) ? 2.f * (A1 - A0) : 2.f * (A0 - A1);
    } else {
        #pragma unroll
        for (int fm = 0; fm < 4; fm++)
            #pragma unroll
            for (int fn = 0; fn < 4; fn++)
                #pragma unroll
                for (int r = 0; r < 4; r++) {
                    int gi = bi * BM + wM * 64 + fm * 16 + gID + (r >> 1) * 8;
                    int gj = bj * BM + wN * 32 + fn * 8 + tig * 2 + (r & 1);
                    float arg = fminf(fmaf(acc[fm][fn][r], tc2,
                                           nsi[fm * 2 + (r >> 1)] + nsj[fn * 2 + (r & 1)]), 0.f);
                    float tt = ex2(arg);
                    float t2 = tt * tt, t4 = t2 * t2, t8 = t4 * t4;
                    float s1 = fmaf(tt, tt, tt);
                    float s2 = fmaf(t4, t4, t4);
                    float ks = (s1 + s2) + t8 * t8;
                    float w = (gj > gi) ? (((gi ^ gj) & 1) ? -2.f : 2.f) : 0.f;
                    part = fmaf(w, ks, part);
                }
    }

    float* s_red = (float*)(sp + OFF_RED);
    s_red[tid] = part;
    __syncthreads();
    #pragma unroll
    for (int o = 128; o > 0; o >>= 1) {
        if (tid < o) s_red[tid] += s_red[tid + o];
        __syncthreads();
    }
    if (tid == 0) {
        atomicAdd(&g_loss, (double)s_red[0]);
        MBAR_INVAL(mbar);
    }
}

__global__ void k_final(float* __restrict__ out) {
    double half = (double)(N / 2);
    out[0] = (float)((g_loss + 5.0 * (double)N) / (half * half));
}

// ---------------- launch ----------------
extern "C" void kernel_launch(void* const* d_in, const int* in_sizes, int n_in,
                              void* d_out, int out_size) {
    const float* x = (const float*)d_in[0];
    float* out = (float*)d_out;

    cudaFuncSetAttribute(k_main, cudaFuncAttributeMaxDynamicSharedMemorySize, SMEM_DYN);

    k_zero   <<<1, 256>>>();
    k_rowsq  <<<N / 8, 256>>>(x);
    k_colsum <<<N / 128, D>>>(x);
    k_convert<<<(N * 24) / 256, 256>>>(x);
    k_const  <<<1, D>>>();
    k_main   <<<NTILES, 256, SMEM_DYN>>>();
    k_final  <<<1, 1>>>(out);
}

// round 4
// speedup vs baseline: 4.3460x; 1.0257x over previous
#include <cuda_runtime.h>
#include <cuda_fp16.h>
#include <cstdint>

#define N        8192
#define D        192
#define BM       128
#define NB       64
#define NTILES   2080             // NB*(NB+1)/2
#define TILE_BYTES (BM * D * 2)   // 49152 fp16 bytes per 128-row tile

// ---------------- device globals ----------------
__device__ double g_loss;
__device__ float  g_sq[N];
__device__ float  g_sqpart[NB];        // per-block sum of row norms
__device__ float  g_colpart[D * NB];   // [col][block] partial column sums
__device__ float  g_c2;                // log2(e) / (16*bandwidth)
__device__ uint4  g_xh[N * D * 2 / 16];// fp16 x, row stride 384B, 16B-group XOR swizzle

// ---------------- helpers ----------------
__device__ __forceinline__ uint32_t smem_u32(const void* p) {
    uint32_t a;
    asm("{ .reg .u64 t; cvta.to.shared.u64 t, %1; cvt.u32.u64 %0, t; }" : "=r"(a) : "l"(p));
    return a;
}
#define MBAR_INIT(a, c) asm volatile("mbarrier.init.shared.b64 [%0], %1;" :: "r"(a), "r"(c) : "memory")
#define MBAR_INVAL(a)   asm volatile("mbarrier.inval.shared.b64 [%0];"    :: "r"(a) : "memory")
#define MBAR_EXPECT_TX(a, b) asm volatile("mbarrier.arrive.expect_tx.shared.b64 _, [%0], %1;" :: "r"(a), "r"(b) : "memory")
#define MBAR_WAIT(a, ph) do { \
    uint32_t _m = (a), _p = (ph), _d; \
    asm volatile("{ .reg .pred p; mbarrier.try_wait.parity.acquire.cta.shared::cta.b64 p, [%1], %2; selp.b32 %0,1,0,p; }" \
        : "=r"(_d) : "r"(_m), "r"(_p) : "memory"); \
    if (!_d) { asm volatile("{ .reg .pred P1; WL_%=: mbarrier.try_wait.parity.acquire.cta.shared::cta.b64 P1, [%0], %1, 0x989680; @P1 bra.uni WD_%=; bra.uni WL_%=; WD_%=: }" \
        :: "r"(_m), "r"(_p) : "memory"); } } while (0)

__device__ __forceinline__ void bulk_g2s(uint32_t dst, const void* src, uint32_t bytes, uint32_t mbar) {
    asm volatile("cp.async.bulk.shared::cluster.global.mbarrier::complete_tx::bytes [%0], [%1], %2, [%3];"
        :: "r"(dst), "l"(src), "r"(bytes), "r"(mbar) : "memory");
}
#define LDSM_X4(r0, r1, r2, r3, a) \
    asm volatile("ldmatrix.sync.aligned.m8n8.x4.shared.b16 {%0,%1,%2,%3}, [%4];" \
        : "=r"(r0), "=r"(r1), "=r"(r2), "=r"(r3) : "r"(a))
// fp16 accumulators: 2x throughput of fp32-acc HMMA
#define MMA16816H(d, a, b0, b1) \
    asm volatile("mma.sync.aligned.m16n8k16.row.col.f16.f16.f16.f16 " \
        "{%0,%1},{%2,%3,%4,%5},{%6,%7},{%0,%1};" \
        : "+r"((d)[0]), "+r"((d)[1]) \
        : "r"((a)[0]), "r"((a)[1]), "r"((a)[2]), "r"((a)[3]), "r"(b0), "r"(b1))
__device__ __forceinline__ float ex2(float x) {
    float r; asm("ex2.approx.ftz.f32 %0, %1;" : "=f"(r) : "f"(x)); return r;
}

// ---------------- fused prologue: convert + row norms + column partials ----------------
__global__ __launch_bounds__(256) void k_prep(const float* __restrict__ x) {
    __shared__ float s_part[256];
    __shared__ float s_row[128];
    int b = blockIdx.x, t = threadIdx.x;
    int r = t >> 1, h = t & 1;
    int gr = b * BM + r;

    const float* src = x + (size_t)gr * D + h * 96;
    char* dstbase = (char*)g_xh + (size_t)gr * 384;
    uint32_t sw = (uint32_t)(gr & 7);

    float sq = 0.f;
    #pragma unroll
    for (int g = 0; g < 12; g++) {
        float4 f0 = *(const float4*)(src + g * 8);
        float4 f1 = *(const float4*)(src + g * 8 + 4);
        sq = fmaf(f0.x, f0.x, sq); sq = fmaf(f0.y, f0.y, sq);
        sq = fmaf(f0.z, f0.z, sq); sq = fmaf(f0.w, f0.w, sq);
        sq = fmaf(f1.x, f1.x, sq); sq = fmaf(f1.y, f1.y, sq);
        sq = fmaf(f1.z, f1.z, sq); sq = fmaf(f1.w, f1.w, sq);
        half2 hh[4];
        hh[0] = __float22half2_rn(make_float2(f0.x, f0.y));
        hh[1] = __float22half2_rn(make_float2(f0.z, f0.w));
        hh[2] = __float22half2_rn(make_float2(f1.x, f1.y));
        hh[3] = __float22half2_rn(make_float2(f1.z, f1.w));
        uint32_t gg = (uint32_t)(h * 12 + g);
        *(uint4*)(dstbase + ((gg ^ sw) << 4)) = *(uint4*)hh;
    }
    s_part[t] = sq;
    __syncthreads();
    if (t < 128) {
        float v = s_part[2 * t] + s_part[2 * t + 1];
        g_sq[b * BM + t] = v;
        s_row[t] = v;
    }
    __syncthreads();
    if (t < 64) s_row[t] += s_row[t + 64];
    __syncthreads();
    if (t < 32) {
        float v = s_row[t] + s_row[t + 32];
        #pragma unroll
        for (int o = 16; o > 0; o >>= 1) v += __shfl_down_sync(0xffffffffu, v, o);
        if (t == 0) g_sqpart[b] = v;
    }
    // column partial sums over this block's 128 rows (x is L2-hot)
    if (t < D) {
        float cs = 0.f;
        #pragma unroll 8
        for (int rr = 0; rr < 128; rr++) cs += x[(size_t)(b * BM + rr) * D + t];
        g_colpart[t * NB + b] = cs;
    }
}

// bandwidth constant + zero the accumulator
__global__ void k_const() {   // 256 threads
    __shared__ float  sh[256];
    __shared__ double s2[64];
    int t = threadIdx.x;
    float cs = 0.f;
    if (t < D) {
        const float* p = g_colpart + t * NB;
        #pragma unroll 8
        for (int b = 0; b < NB; b++) cs += p[b];
    }
    sh[t] = cs * cs;
    if (t < 64) s2[t] = (double)g_sqpart[t];
    __syncthreads();
    if (t == 0) {
        double ss = 0.0;
        for (int i = 0; i < 256; i++) ss += (double)sh[i];
        double sumsq = 0.0;
        for (int i = 0; i < 64; i++) sumsq += s2[i];
        double sumL2 = 2.0 * (double)N * sumsq - 2.0 * ss;
        double bw = sumL2 / ((double)N * (double)N - (double)N);
        bw *= 0.25;                                       // / KERNEL_MUL^(KERNEL_NUM//2)
        g_c2 = (float)(1.4426950408889634 / (bw * 16.0));
        g_loss = 0.0;
    }
}

// ---------------- main HMMA tile kernel ----------------
#define OFF_SQI  0
#define OFF_SQJ  512
#define OFF_MBAR 1024
#define OFF_RED  1088
#define OFF_A    3072
#define OFF_B    52224
#define SMEM_DYN (101376 + 1024)

__global__ __launch_bounds__(256, 2) void k_main() {
    extern __shared__ char dsm[];
    uint32_t sb = (smem_u32(dsm) + 1023u) & ~1023u;
    char* sp = dsm + (sb - smem_u32(dsm));

    int tid  = threadIdx.x;
    int wid  = tid >> 5, lane = tid & 31;
    int wM   = wid >> 2;          // 0..1 -> 64 rows
    int wN   = wid & 3;           // 0..3 -> 32 cols
    int gID  = lane >> 2;
    int tig  = lane & 3;

    int t = blockIdx.x, bi = 0, rem = t;
    while (rem >= NB - bi) { rem -= NB - bi; bi++; }
    int bj = bi + rem;
    bool diag = (bi == bj);

    uint32_t mbar = sb + OFF_MBAR;
    if (tid == 0) MBAR_INIT(mbar, 1);

    if (tid < 128) ((float*)(sp + OFF_SQI))[tid] = g_sq[bi * BM + tid];
    else           ((float*)(sp + OFF_SQJ))[tid - 128] = g_sq[bj * BM + tid - 128];
    __syncthreads();

    if (tid == 0) {
        MBAR_EXPECT_TX(mbar, 2 * TILE_BYTES);
        const char* xh = (const char*)g_xh;
        bulk_g2s(sb + OFF_A, xh + (size_t)bi * TILE_BYTES, TILE_BYTES, mbar);
        bulk_g2s(sb + OFF_B, xh + (size_t)bj * TILE_BYTES, TILE_BYTES, mbar);
    }

    uint32_t accH[4][4][2];
    #pragma unroll
    for (int a = 0; a < 4; a++)
        #pragma unroll
        for (int b = 0; b < 4; b++) { accH[a][b][0] = 0u; accH[a][b][1] = 0u; }

    uint32_t swz   = (uint32_t)(lane & 7);
    uint32_t ahi   = (uint32_t)(lane >> 4);
    uint32_t bhi   = (uint32_t)((lane >> 3) & 1);
    uint32_t baseA = sb + OFF_A + (uint32_t)(wM * 64 + (lane & 15)) * 384u;
    uint32_t baseB = sb + OFF_B + (uint32_t)(wN * 32 + ((lane >> 4) << 3) + (lane & 7)) * 384u;

    MBAR_WAIT(mbar, 0);

    #pragma unroll
    for (int kg = 0; kg < 12; kg++) {
        uint32_t a[4][4], b[2][4];
        uint32_t ga = (uint32_t)(2 * kg) + ahi;
        uint32_t gb = (uint32_t)(2 * kg) + bhi;
        #pragma unroll
        for (int fm = 0; fm < 4; fm++) {
            uint32_t ad = baseA + (uint32_t)fm * 6144u + ((ga ^ swz) << 4);
            LDSM_X4(a[fm][0], a[fm][1], a[fm][2], a[fm][3], ad);
        }
        #pragma unroll
        for (int q = 0; q < 2; q++) {
            uint32_t bd = baseB + (uint32_t)q * 6144u + ((gb ^ swz) << 4);
            LDSM_X4(b[q][0], b[q][1], b[q][2], b[q][3], bd);
        }
        #pragma unroll
        for (int fm = 0; fm < 4; fm++)
            #pragma unroll
            for (int fn = 0; fn < 4; fn++)
                MMA16816H(accH[fm][fn], a[fm], b[fn >> 1][(fn & 1) * 2], b[fn >> 1][(fn & 1) * 2 + 1]);
    }

    // ---------------- fused MMD epilogue ----------------
    float c2 = g_c2, tc2 = 2.f * c2, nc2 = -c2;
    const float* s_sqi = (const float*)(sp + OFF_SQI);
    const float* s_sqj = (const float*)(sp + OFF_SQJ);

    float nsi[8], nsj[8];
    #pragma unroll
    for (int fm = 0; fm < 4; fm++) {
        nsi[fm * 2 + 0] = nc2 * s_sqi[wM * 64 + fm * 16 + gID];
        nsi[fm * 2 + 1] = nc2 * s_sqi[wM * 64 + fm * 16 + gID + 8];
    }
    #pragma unroll
    for (int fn = 0; fn < 4; fn++) {
        nsj[fn * 2 + 0] = nc2 * s_sqj[wN * 32 + fn * 8 + tig * 2];
        nsj[fn * 2 + 1] = nc2 * s_sqj[wN * 32 + fn * 8 + tig * 2 + 1];
    }

    float part = 0.f;
    if (!diag) {
        float A0 = 0.f, A1 = 0.f;
        #pragma unroll
        for (int fm = 0; fm < 4; fm++)
            #pragma unroll
            for (int fn = 0; fn < 4; fn++) {
                float2 p0 = __half22float2(*(half2*)&accH[fm][fn][0]);
                float2 p1 = __half22float2(*(half2*)&accH[fm][fn][1]);
                float dots[4] = {p0.x, p0.y, p1.x, p1.y};
                #pragma unroll
                for (int r = 0; r < 4; r++) {
                    float arg = fminf(fmaf(dots[r], tc2,
                                           nsi[fm * 2 + (r >> 1)] + nsj[fn * 2 + (r & 1)]), 0.f);
                    float tt = ex2(arg);
                    float t4 = (tt * tt) * (tt * tt);
                    float s1 = fmaf(tt, tt, tt);       // t + t^2
                    float s2 = fmaf(t4, t4, t4);       // t^4 + t^8
                    float t8 = t4 * t4;
                    float ks = (s1 + s2) + t8 * t8;    // + t^16
                    if (r & 1) A1 += ks; else A0 += ks;
                }
            }
        part = (gID & 1) ? 2.f * (A1 - A0) : 2.f * (A0 - A1);
    } else {
        #pragma unroll
        for (int fm = 0; fm < 4; fm++)
            #pragma unroll
            for (int fn = 0; fn < 4; fn++) {
                float2 p0 = __half22float2(*(half2*)&accH[fm][fn][0]);
                float2 p1 = __half22float2(*(half2*)&accH[fm][fn][1]);
                float dots[4] = {p0.x, p0.y, p1.x, p1.y};
                #pragma unroll
                for (int r = 0; r < 4; r++) {
                    int gi = bi * BM + wM * 64 + fm * 16 + gID + (r >> 1) * 8;
                    int gj = bj * BM + wN * 32 + fn * 8 + tig * 2 + (r & 1);
                    float arg = fminf(fmaf(dots[r], tc2,
                                           nsi[fm * 2 + (r >> 1)] + nsj[fn * 2 + (r & 1)]), 0.f);
                    float tt = ex2(arg);
                    float t4 = (tt * tt) * (tt * tt);
                    float s1 = fmaf(tt, tt, tt);
                    float s2 = fmaf(t4, t4, t4);
                    float t8 = t4 * t4;
                    float ks = (s1 + s2) + t8 * t8;
                    float w = (gj > gi) ? (((gi ^ gj) & 1) ? -2.f : 2.f) : 0.f;
                    part = fmaf(w, ks, part);
                }
            }
    }

    // warp reduce -> one double atomic per CTA
    #pragma unroll
    for (int o = 16; o > 0; o >>= 1) part += __shfl_xor_sync(0xffffffffu, part, o);
    float* s_red = (float*)(sp + OFF_RED);
    if (lane == 0) s_red[wid] = part;
    __syncthreads();
    if (tid == 0) {
        float s = 0.f;
        #pragma unroll
        for (int w = 0; w < 8; w++) s += s_red[w];
        atomicAdd(&g_loss, (double)s);
        MBAR_INVAL(mbar);
    }
}

__global__ void k_final(float* __restrict__ out) {
    double half = (double)(N / 2);
    out[0] = (float)((g_loss + 5.0 * (double)N) / (half * half));
}

// ---------------- launch ----------------
extern "C" void kernel_launch(void* const* d_in, const int* in_sizes, int n_in,
                              void* d_out, int out_size) {
    const float* x = (const float*)d_in[0];
    float* out = (float*)d_out;

    cudaFuncSetAttribute(k_main, cudaFuncAttributeMaxDynamicSharedMemorySize, SMEM_DYN);

    k_prep  <<<NB, 256>>>(x);
    k_const <<<1, 256>>>();
    k_main  <<<NTILES, 256, SMEM_DYN>>>();
    k_final <<<1, 1>>>(out);
}